// round 1
// baseline (speedup 1.0000x reference)
#include <cuda_runtime.h>

#define BB   8192
#define JJ   16
#define NHID 128
#define NS4  (4*BB)                 // 32768 samples in branch phase
#define NRMAX (NS4*JJ)              // 524288 rows
#define EPSB 1e-5f

// ---------------- persistent scratch (device globals; no allocation) ----------------
__device__ float  g_H [NRMAX*NHID];   // pre-BN gconv output
__device__ float  g_X0[NRMAX*NHID];   // activation ping
__device__ float  g_X1[NRMAX*NHID];   // activation pong
__device__ float  g_Y1[NRMAX*NHID];   // joint-mixed input for next gemm
__device__ float  g_merged[BB*JJ*12];
__device__ float  g_att[15*JJ*JJ];    // 0:in 1:cat 2..9:res 10..14:out
__device__ double g_sum  [4*NHID];
__device__ double g_sumsq[4*NHID];
__device__ float  g_mu  [4*NHID];
__device__ float  g_istd[4*NHID];

// hardcoded H36M 16-joint mask (eye + edges), row i -> bitmask over j
__constant__ unsigned short c_mask[16] = {
 0x0093,0x0007,0x000E,0x000C,0x0031,0x0070,0x0060,0x0181,
 0x4B80,0x0700,0x0600,0x1900,0x3800,0x3000,0xC100,0xC000};

// ---------------- prep: masked softmax for all 15 attention matrices ----------------
__global__ void sg_prep(const float* __restrict__ e_in, const float* __restrict__ e_cat,
                        const float* __restrict__ e_res, const float* __restrict__ e_out)
{
    int t = threadIdx.x;
    for (int i = t; i < 4*NHID; i += 256) { g_sum[i] = 0.0; g_sumsq[i] = 0.0; }
    if (t < 240) {
        int slot = t >> 4, i = t & 15;
        const float* e;
        if (slot == 0)      e = e_in;
        else if (slot == 1) e = e_cat;
        else if (slot < 10) e = e_res + (slot-2)*256;
        else                e = e_out + (slot-10)*256;
        unsigned m = c_mask[i];
        float mx = -1e30f;
        for (int j = 0; j < 16; j++) if ((m>>j)&1) mx = fmaxf(mx, e[i*16+j]);
        float v[16]; float s = 0.f;
        for (int j = 0; j < 16; j++) {
            float x = ((m>>j)&1) ? expf(e[i*16+j]-mx) : 0.f;
            v[j] = x; s += x;
        }
        float inv = 1.f/s;
        for (int j = 0; j < 16; j++) g_att[slot*256 + i*16 + j] = v[j]*inv;
    }
}

// ---------------- small-K input gconv (K=2 branch-in, K=12 concat-in) ----------------
// mixes in input space, then h = y0@W0 + y1@W1 + b ; accumulates BN stats per set.
template<int KIN>
__global__ void sg_gconv_smallk(const float* __restrict__ x0, const float* __restrict__ x1,
                                const float* __restrict__ x2, const float* __restrict__ x3,
                                int fourway, const float* __restrict__ W,
                                const float* __restrict__ bias, int attSlot,
                                float* __restrict__ H)
{
    __shared__ float xs [8][16][KIN];
    __shared__ float y0s[8][16][KIN];
    __shared__ float y1s[8][16][KIN];
    __shared__ float Ws[2*KIN*NHID];
    __shared__ float attS[256];
    int t  = threadIdx.x;              // 128
    int s0 = blockIdx.x * 8;
    int set = blockIdx.x >> 10;        // 128 rows/block, 131072 rows/set

    for (int i = t; i < 2*KIN*NHID; i += 128) Ws[i] = W[i];
    for (int i = t; i < 256; i += 128) attS[i] = g_att[attSlot*256 + i];

    const int total = 8*16*KIN;
    for (int i = t; i < total; i += 128) {
        int s = i/(16*KIN); int rem = i - s*16*KIN; int j = rem/KIN; int k = rem - j*KIN;
        int gs = s0 + s;
        const float* xp; int loc;
        if (fourway) {
            int br = gs >> 13; loc = gs & (BB-1);
            xp = (br==0)?x0:(br==1)?x1:(br==2)?x2:x3;
        } else { xp = x0; loc = gs; }
        xs[s][j][k] = xp[(loc*16 + j)*KIN + k];
    }
    __syncthreads();
    for (int i = t; i < total; i += 128) {
        int s = i/(16*KIN); int rem = i - s*16*KIN; int ji = rem/KIN; int k = rem - ji*KIN;
        float a1 = 0.f;
        #pragma unroll
        for (int j = 0; j < 16; j++) a1 += attS[ji*16+j]*xs[s][j][k];
        a1 -= attS[ji*17]*xs[s][ji][k];
        y0s[s][ji][k] = attS[ji*17]*xs[s][ji][k];
        y1s[s][ji][k] = a1;
    }
    __syncthreads();
    int c = t;
    float w0[KIN], w1[KIN];
    #pragma unroll
    for (int k = 0; k < KIN; k++) { w0[k] = Ws[k*NHID+c]; w1[k] = Ws[(KIN+k)*NHID+c]; }
    float bb = bias[c];
    float bsum = 0.f, bsq = 0.f;
    for (int s = 0; s < 8; s++)
        for (int ji = 0; ji < 16; ji++) {
            float h = bb;
            #pragma unroll
            for (int k = 0; k < KIN; k++) h += y0s[s][ji][k]*w0[k] + y1s[s][ji][k]*w1[k];
            H[((s0+s)*16 + ji)*NHID + c] = h;
            bsum += h; bsq += h*h;
        }
    atomicAdd(&g_sum  [set*NHID + c], (double)bsum);
    atomicAdd(&g_sumsq[set*NHID + c], (double)bsq);
}

// ---------------- BN stat finalize (one block per set) ----------------
__global__ void sg_bn_finalize(float invN)
{
    int idx = blockIdx.x*NHID + threadIdx.x;
    double s = g_sum[idx], q = g_sumsq[idx];
    float mu  = (float)(s*(double)invN);
    float var = (float)(q*(double)invN) - mu*mu;
    g_mu[idx] = mu; g_istd[idx] = rsqrtf(var + EPSB);
    g_sum[idx] = 0.0; g_sumsq[idx] = 0.0;
}

// ---------------- BN apply + ReLU (+residual) + joint mix for next stage --------------
__global__ void sg_bn_mix(const float* __restrict__ H, const float* __restrict__ R,
                          float* __restrict__ Xout, float* __restrict__ Y1out,
                          const float* __restrict__ gma, const float* __restrict__ bta,
                          int attSlot, int makeY1)
{
    __shared__ float xn[4*16*128];     // 4 samples
    __shared__ float attS[256];
    __shared__ float muS[128], isS[128], gS[128], bS[128];
    int t = threadIdx.x;               // 256
    int set = blockIdx.x >> 11;        // 64 rows/block, 131072 rows/set
    if (t < 128) {
        muS[t] = g_mu[set*NHID+t]; isS[t] = g_istd[set*NHID+t];
        gS[t]  = gma[t];           bS[t]  = bta[t];
    }
    attS[t] = g_att[attSlot*256 + t];
    __syncthreads();
    long base = (long)blockIdx.x * 8192;
    for (int i = t; i < 8192; i += 256) {
        int c = i & 127;
        float v = H[base + i];
        v = fmaxf((v - muS[c])*isS[c]*gS[c] + bS[c], 0.f);
        if (R) v += R[base + i];
        xn[i] = v;
        Xout[base + i] = v;
    }
    __syncthreads();
    if (makeY1) {
        for (int i = t; i < 8192; i += 256) {
            int c = i & 127; int ji = (i >> 7) & 15; int s = i >> 11;
            const float* xr = xn + s*2048;
            float a = 0.f;
            #pragma unroll
            for (int j = 0; j < 16; j++) a += attS[ji*16+j]*xr[j*128 + c];
            a -= attS[ji*17]*xr[ji*128 + c];
            Y1out[base + i] = a;
        }
    }
}

// ---------------- main gemm: out = (d_i * X)@W0 + Y1@W1 + b, K=256 ----------------
#define GEMM_SMEM_FLOATS (256*128 + 2*8*132 + 256)
#define GEMM_SMEM_BYTES  (GEMM_SMEM_FLOATS*4)

__global__ __launch_bounds__(256) void sg_gemm128(
    const float* __restrict__ X, const float* __restrict__ Y1,
    const float* __restrict__ W, const float* __restrict__ bias,
    int attSlot, float* __restrict__ H)
{
    extern __shared__ float sm[];
    float* Ws   = sm;                  // [256][128]
    float* As   = sm + 256*128;        // 2 buffers of [8][132]
    float* sSum = As + 2*8*132;        // [128]
    float* sSq  = sSum + 128;          // [128]
    __shared__ float dS[16];
    __shared__ float bS[128];

    int tid = threadIdx.x;
    int tx = tid & 15, ty = tid >> 4;
    int blockRow0 = blockIdx.x * 128;
    int set = blockIdx.x >> 10;

    {   // whole weight matrix resident in smem
        const float4* W4 = (const float4*)W;
        float4* Ws4 = (float4*)Ws;
        #pragma unroll
        for (int i = 0; i < 32; i++) Ws4[tid + i*256] = W4[tid + i*256];
    }
    if (tid < 16)  dS[tid] = g_att[attSlot*256 + tid*17];
    if (tid < 128) { bS[tid] = bias[tid]; sSum[tid] = 0.f; sSq[tid] = 0.f; }
    __syncthreads();

    int r = tid >> 1, half = tid & 1;
    const float dsc = dS[r & 15];
    long rowBase = (long)(blockRow0 + r) * 128;

    float acc[8][8];
    #pragma unroll
    for (int i = 0; i < 8; i++)
        #pragma unroll
        for (int j = 0; j < 8; j++) acc[i][j] = 0.f;

    // tile 0
    {
        int k0 = half*4;
        float4 v = *(const float4*)(X + rowBase + k0);
        v.x *= dsc; v.y *= dsc; v.z *= dsc; v.w *= dsc;
        As[(k0+0)*132+r]=v.x; As[(k0+1)*132+r]=v.y; As[(k0+2)*132+r]=v.z; As[(k0+3)*132+r]=v.w;
    }
    __syncthreads();

    for (int tt = 0; tt < 32; tt++) {
        float4 nx;
        if (tt < 31) {
            int k0 = (tt+1)*8 + half*4;
            if (tt+1 < 16) {
                nx = *(const float4*)(X + rowBase + k0);
                nx.x*=dsc; nx.y*=dsc; nx.z*=dsc; nx.w*=dsc;
            } else {
                nx = *(const float4*)(Y1 + rowBase + (k0-128));
            }
        }
        const float* a  = As + (tt & 1)*1056;
        const float* wB = Ws + tt*8*128;
        #pragma unroll
        for (int kk = 0; kk < 8; kk++) {
            const float4* a4 = (const float4*)(a + kk*132 + ty*8);
            const float4* b4 = (const float4*)(wB + kk*128 + tx*8);
            float4 p = a4[0], q = a4[1];
            float4 u = b4[0], w = b4[1];
            float av[8] = {p.x,p.y,p.z,p.w,q.x,q.y,q.z,q.w};
            float bv[8] = {u.x,u.y,u.z,u.w,w.x,w.y,w.z,w.w};
            #pragma unroll
            for (int i = 0; i < 8; i++)
                #pragma unroll
                for (int j = 0; j < 8; j++) acc[i][j] += av[i]*bv[j];
        }
        if (tt < 31) {
            float* an = As + ((tt+1)&1)*1056;
            int kk = half*4;
            an[(kk+0)*132+r]=nx.x; an[(kk+1)*132+r]=nx.y; an[(kk+2)*132+r]=nx.z; an[(kk+3)*132+r]=nx.w;
            __syncthreads();
        }
    }

    // epilogue: bias, store H, per-channel stats
    int c0 = tx*8, r0 = ty*8;
    float cs[8], cq[8];
    #pragma unroll
    for (int j = 0; j < 8; j++) { cs[j] = 0.f; cq[j] = 0.f; }
    #pragma unroll
    for (int i = 0; i < 8; i++) {
        float o[8];
        #pragma unroll
        for (int j = 0; j < 8; j++) {
            float v = acc[i][j] + bS[c0+j];
            o[j] = v; cs[j] += v; cq[j] += v*v;
        }
        long row = (long)(blockRow0 + r0 + i);
        float4* Hp = (float4*)(H + row*128 + c0);
        Hp[0] = make_float4(o[0],o[1],o[2],o[3]);
        Hp[1] = make_float4(o[4],o[5],o[6],o[7]);
    }
    #pragma unroll
    for (int j = 0; j < 8; j++) { atomicAdd(&sSum[c0+j], cs[j]); atomicAdd(&sSq[c0+j], cq[j]); }
    __syncthreads();
    if (tid < 128) {
        atomicAdd(&g_sum  [set*NHID + tid], (double)sSum[tid]);
        atomicAdd(&g_sumsq[set*NHID + tid], (double)sSq[tid]);
    }
}

// ---------------- output semgconv (128 -> 3), per-branch weights/attention ------------
__global__ void sg_gconv_out(const float* __restrict__ X, const float* __restrict__ Wout,
                             const float* __restrict__ bout, int finalMode,
                             float* __restrict__ outp, float* __restrict__ merged)
{
    __shared__ float xs[4*16*129];
    __shared__ float Wl[768];
    __shared__ float attL[256];
    __shared__ float h1s[4][16][3];
    __shared__ float bL[3];
    int t  = threadIdx.x;              // 128
    int s0 = blockIdx.x * 4;
    int branch = finalMode ? 4 : (s0 >> 13);

    for (int i = t; i < 768; i += 128) Wl[i] = Wout[branch*768 + i];
    for (int i = t; i < 256; i += 128) attL[i] = g_att[(10+branch)*256 + i];
    if (t < 3) bL[t] = bout[branch*3 + t];
    for (int i = t; i < 4*16*128; i += 128) {
        int s = i >> 11, rem = i & 2047, j = rem >> 7, k = rem & 127;
        xs[(s*16+j)*129 + k] = X[((long)(s0+s)*16 + j)*128 + k];
    }
    __syncthreads();

    int si = t >> 4, ji = t & 15;
    float h0[3] = {0.f,0.f,0.f};
    if (t < 64) {
        float h1[3] = {0.f,0.f,0.f};
        const float* xr = xs + (si*16 + ji)*129;
        for (int k = 0; k < 128; k++) {
            float x = xr[k];
            h0[0] += x*Wl[k*3+0]; h0[1] += x*Wl[k*3+1]; h0[2] += x*Wl[k*3+2];
            h1[0] += x*Wl[384+k*3+0]; h1[1] += x*Wl[384+k*3+1]; h1[2] += x*Wl[384+k*3+2];
        }
        h1s[si][ji][0]=h1[0]; h1s[si][ji][1]=h1[1]; h1s[si][ji][2]=h1[2];
    }
    __syncthreads();
    if (t < 64) {
        float dd = attL[ji*17];
        float o[3];
        #pragma unroll
        for (int c = 0; c < 3; c++) o[c] = dd*h0[c] + bL[c];
        #pragma unroll
        for (int j = 0; j < 16; j++) {
            if (j == ji) continue;
            float a = attL[ji*16 + j];
            o[0] += a*h1s[si][j][0]; o[1] += a*h1s[si][j][1]; o[2] += a*h1s[si][j][2];
        }
        if (finalMode) {
            long row = ((long)(s0+si)*16 + ji)*3;
            outp[row+0]=o[0]; outp[row+1]=o[1]; outp[row+2]=o[2];
        } else {
            int loc = (s0+si) & (BB-1);
            long ob = (long)(1+branch)*BB*48 + ((long)loc*16 + ji)*3;
            outp[ob+0]=o[0]; outp[ob+1]=o[1]; outp[ob+2]=o[2];
            long mb = ((long)loc*16 + ji)*12 + branch*3;
            merged[mb+0]=o[0]; merged[mb+1]=o[1]; merged[mb+2]=o[2];
        }
    }
}

// ---------------- host orchestration ----------------
extern "C" void kernel_launch(void* const* d_in, const int* in_sizes, int n_in,
                              void* d_out, int out_size)
{
    const float* x1       = (const float*)d_in[0];
    const float* x2       = (const float*)d_in[1];
    const float* x3       = (const float*)d_in[2];
    const float* x4       = (const float*)d_in[3];
    const float* W_in     = (const float*)d_in[4];
    const float* b_in     = (const float*)d_in[5];
    const float* e_in     = (const float*)d_in[6];
    const float* g_in     = (const float*)d_in[7];
    const float* beta_in  = (const float*)d_in[8];
    const float* W_cat    = (const float*)d_in[9];
    const float* b_cat    = (const float*)d_in[10];
    const float* e_cat    = (const float*)d_in[11];
    const float* g_cat    = (const float*)d_in[12];
    const float* beta_cat = (const float*)d_in[13];
    const float* W_res    = (const float*)d_in[14];
    const float* b_res    = (const float*)d_in[15];
    const float* e_res    = (const float*)d_in[16];
    const float* g_res    = (const float*)d_in[17];
    const float* beta_res = (const float*)d_in[18];
    const float* W_out    = (const float*)d_in[19];
    const float* b_out    = (const float*)d_in[20];
    const float* e_out    = (const float*)d_in[21];
    float* out = (float*)d_out;

    float *Hb, *X0b, *X1b, *Y1b, *Mb;
    cudaGetSymbolAddress((void**)&Hb,  g_H);
    cudaGetSymbolAddress((void**)&X0b, g_X0);
    cudaGetSymbolAddress((void**)&X1b, g_X1);
    cudaGetSymbolAddress((void**)&Y1b, g_Y1);
    cudaGetSymbolAddress((void**)&Mb,  g_merged);

    cudaFuncSetAttribute(sg_gemm128, cudaFuncAttributeMaxDynamicSharedMemorySize, GEMM_SMEM_BYTES);

    sg_prep<<<1,256>>>(e_in, e_cat, e_res, e_out);

    const float invN = 1.f / (float)(BB*JJ);   // per-branch BN count == 131072 in both phases

    // ===== phase 1: 4 branches batched (32768 samples, 4 BN-stat sets) =====
    {
        int nS = NS4, nRows = nS*JJ, nSets = 4;
        sg_gconv_smallk<2><<<nS/8,128>>>(x1,x2,x3,x4, 1, W_in, b_in, 0, Hb);
        sg_bn_finalize<<<nSets,128>>>(invN);
        sg_bn_mix<<<nRows/64,256>>>(Hb, nullptr, X0b, Y1b, g_in, beta_in, 2, 1);
        for (int s = 0; s < 8; s++) {
            const float* Xin = (s & 1) ? X1b : X0b;
            sg_gemm128<<<nRows/128,256,GEMM_SMEM_BYTES>>>(Xin, Y1b, W_res + s*2*128*128,
                                                          b_res + s*128, 2+s, Hb);
            sg_bn_finalize<<<nSets,128>>>(invN);
            float* Xo       = (s & 1) ? X0b : X1b;
            const float* Rb = (s & 1) ? X0b : nullptr;
            int nextAtt = (s < 7) ? (3+s) : 0;
            sg_bn_mix<<<nRows/64,256>>>(Hb, Rb, Xo, Y1b, g_res + s*128, beta_res + s*128,
                                        nextAtt, (s < 7) ? 1 : 0);
        }
        sg_gconv_out<<<nS/4,128>>>(X0b, W_out, b_out, 0, out, Mb);   // out1..out4 + merged
    }

    // ===== phase 2: concat branch (8192 samples, 1 BN-stat set) =====
    {
        int nS = BB, nRows = nS*JJ, nSets = 1;
        sg_gconv_smallk<12><<<nS/8,128>>>(Mb, nullptr, nullptr, nullptr, 0, W_cat, b_cat, 1, Hb);
        sg_bn_finalize<<<nSets,128>>>(invN);
        sg_bn_mix<<<nRows/64,256>>>(Hb, nullptr, X0b, Y1b, g_cat, beta_cat, 2, 1);
        for (int s = 0; s < 8; s++) {
            const float* Xin = (s & 1) ? X1b : X0b;
            sg_gemm128<<<nRows/128,256,GEMM_SMEM_BYTES>>>(Xin, Y1b, W_res + s*2*128*128,
                                                          b_res + s*128, 2+s, Hb);
            sg_bn_finalize<<<nSets,128>>>(invN);
            float* Xo       = (s & 1) ? X0b : X1b;
            const float* Rb = (s & 1) ? X0b : nullptr;
            int nextAtt = (s < 7) ? (3+s) : 0;
            sg_bn_mix<<<nRows/64,256>>>(Hb, Rb, Xo, Y1b, g_res + s*128, beta_res + s*128,
                                        nextAtt, (s < 7) ? 1 : 0);
        }
        sg_gconv_out<<<nS/4,128>>>(X0b, W_out, b_out, 1, out, nullptr); // out_final at offset 0
    }
}